// round 6
// baseline (speedup 1.0000x reference)
#include <cuda_runtime.h>

#define COLS 8192
#define TPB  256
#define EPT  32            // 256*32 = 8192

__device__ __forceinline__ float ex2f(float x) {
    float y; asm("ex2.approx.ftz.f32 %0, %1;" : "=f"(y) : "f"(x)); return y;
}
__device__ __forceinline__ float lg2f(float x) {
    float y; asm("lg2.approx.ftz.f32 %0, %1;" : "=f"(y) : "f"(x)); return y;
}

// One-barrier block sum: every thread STS; after the barrier EVERY warp
// redundantly reduces all 256 partials (2x LDS.128 + adds + shfl tree) and
// every thread returns the full sum. No warp0 serialization, no broadcast.
// Caller double-buffers: a lagging reader of buf[p] is separated from the
// next writer of buf[p] by the intervening round's barrier.
__device__ __forceinline__ float block_sum(float part, float* buf, int tid, int lane) {
    buf[tid] = part;
    __syncthreads();
    const float4* r4 = (const float4*)buf;
    float4 a = r4[lane * 2], b = r4[lane * 2 + 1];
    float x = ((a.x + a.y) + (a.z + a.w)) + ((b.x + b.y) + (b.z + b.w));
    #pragma unroll
    for (int o = 16; o; o >>= 1) x += __shfl_xor_sync(0xffffffffu, x, o);
    return x;
}

// Annealed pass at stride ST over the register row (stratified subsample),
// scaled by ST. CAP: apply min(s, na) (false only before anything can cap).
template<int ST, int CAP>
__device__ __forceinline__ float pass_sum(const float* s, float na, float Kt) {
    float l0 = 0.f, l1 = 0.f;
    #pragma unroll
    for (int j = 0; j < EPT; j += 2 * ST) {
        float x0 = CAP ? fminf(s[j],      na) : s[j];
        float x1 = CAP ? fminf(s[j + ST], na) : s[j + ST];
        l0 += ex2f(x0 * Kt);
        l1 += ex2f(x1 * Kt);
    }
    return (l0 + l1) * (float)ST;
}

__global__ void __launch_bounds__(TPB, 4)
normalizer_kernel(const float* __restrict__ score,
                  const int*   __restrict__ mask,
                  float*       __restrict__ out) {
    __shared__ float4 red4[TPB];     // stats round only
    __shared__ float  red[2][TPB];   // scalar rounds, double-buffered

    const int tid  = threadIdx.x;
    const int lane = tid & 31;
    const size_t base = (size_t)blockIdx.x * COLS;

    const float4* s4 = (const float4*)(score + base);
    const int4*   m4 = (const int4*)(mask + base);

    // ---- load + mask + stats (masked -> -1e30: exp->0, never capped) ----
    float s[EPT];
    float cnt = 0.f, sm = 0.f, mx = -1e30f;
    #pragma unroll
    for (int i = 0; i < EPT / 4; i++) {
        float4 v = s4[i * TPB + tid];
        int4   m = m4[i * TPB + tid];
        s[4*i+0] = m.x ? v.x : -1e30f;  cnt += m.x ? 1.f : 0.f;  sm += m.x ? v.x : 0.f;
        s[4*i+1] = m.y ? v.y : -1e30f;  cnt += m.y ? 1.f : 0.f;  sm += m.y ? v.y : 0.f;
        s[4*i+2] = m.z ? v.z : -1e30f;  cnt += m.z ? 1.f : 0.f;  sm += m.z ? v.z : 0.f;
        s[4*i+3] = m.w ? v.w : -1e30f;  cnt += m.w ? 1.f : 0.f;  sm += m.w ? v.w : 0.f;
        mx = fmaxf(fmaxf(mx, fmaxf(s[4*i+0], s[4*i+1])), fmaxf(s[4*i+2], s[4*i+3]));
    }

    // ---- stats round: (count, sum, max) in one barrier ----
    red4[tid] = make_float4(cnt, sm, mx, 0.f);
    __syncthreads();
    float c0 = 0.f, c1 = 0.f, c2 = -1e30f;
    #pragma unroll
    for (int i = 0; i < 8; i++) {
        float4 v = red4[lane * 8 + i];
        c0 += v.x;  c1 += v.y;  c2 = fmaxf(c2, v.z);
    }
    #pragma unroll
    for (int o = 16; o; o >>= 1) {
        c0 += __shfl_xor_sync(0xffffffffu, c0, o);
        c1 += __shfl_xor_sync(0xffffffffu, c1, o);
        c2 = fmaxf(c2, __shfl_xor_sync(0xffffffffu, c2, o));
    }
    const float invk  = __fdividef(10.0f, c0);       // 1/(0.1*n)
    const float smean = __fdividef(c1, c0);
    // Jensen: na_t >= theta_t*ln10 + smean for t=0..2 (uncapped sums).
    // theta2*ln10 = 4.513; margin 0.06. If it clears s_max, rounds 0-2 cap
    // nothing -> they have NO effect on the iteration. Exact skip.
    const bool  skip  = (smean + 4.45f >= c2);

    const float L2E = 1.44269504088896340736f;
    const float LN2 = 0.6931471805599453f;
    // theta_t = max(0.7^t*4, 0.3): distinct t=0..7, then 0.3 for t=8..19.
    const float TH[8] = {4.0f, 2.8f, 1.96f, 1.372f, 0.9604f,
                         0.67228f, 0.470596f, 0.3294172f};

    int pb = 0;
    float na;   // na = -a = theta*ln2*log2(S*invk)

    if (skip) {
        // t3 directly, uncapped, 1/4 subsample
        float S = block_sum(pass_sum<4,0>(s, 0.f, L2E / TH[3]), red[pb], tid, lane); pb ^= 1;
        na = (TH[3] * LN2) * lg2f((S + 1e-20f) * invk);
    } else {
        // fallback: t0 (b=0) then t1..t3 capped, all 1/4 subsample
        float S = block_sum(pass_sum<4,0>(s, 0.f, L2E / TH[0]), red[pb], tid, lane); pb ^= 1;
        na = (TH[0] * LN2) * lg2f((S + 1e-20f) * invk);
        #pragma unroll
        for (int t = 1; t < 4; t++) {
            S = block_sum(pass_sum<4,1>(s, na, L2E / TH[t]), red[pb], tid, lane); pb ^= 1;
            na = (TH[t] * LN2) * lg2f((S + 1e-20f) * invk);
        }
    }
    // t4, t5 @ 1/4
    #pragma unroll
    for (int t = 4; t < 6; t++) {
        float S = block_sum(pass_sum<4,1>(s, na, L2E / TH[t]), red[pb], tid, lane); pb ^= 1;
        na = (TH[t] * LN2) * lg2f((S + 1e-20f) * invk);
    }
    // t6 @ 1/2
    {
        float S = block_sum(pass_sum<2,1>(s, na, L2E / TH[6]), red[pb], tid, lane); pb ^= 1;
        na = (TH[6] * LN2) * lg2f((S + 1e-20f) * invk);
    }
    // t7 full
    {
        float S = block_sum(pass_sum<1,1>(s, na, L2E / TH[7]), red[pb], tid, lane); pb ^= 1;
        na = (TH[7] * LN2) * lg2f((S + 1e-20f) * invk);
    }

    // ---- convert in place: s := exp(s/0.3) (monotone; min commutes) ----
    const float K03 = L2E / 0.3f;
    #pragma unroll
    for (int j = 0; j < EPT; j++) s[j] = ex2f(s[j] * K03);

    // ---- t=8..19 (theta=0.3): term = min(e,c); scalar update collapses:
    //      c_next = exp(-a_next/0.3) = S/k exactly. MUFU-free, divide-free.
    //      Packed f32x2 accumulation halves the adds. ----
    float c = ex2f(na * K03);
    #pragma unroll 1
    for (int t = 0; t < 12; t++) {
        unsigned long long A = 0ull, B = 0ull;
        #pragma unroll
        for (int j = 0; j < EPT; j += 4) {
            float m0 = fminf(s[j+0], c), m1 = fminf(s[j+1], c);
            float m2 = fminf(s[j+2], c), m3 = fminf(s[j+3], c);
            unsigned long long p0, p1;
            asm("mov.b64 %0, {%1, %2};" : "=l"(p0) : "f"(m0), "f"(m1));
            asm("mov.b64 %0, {%1, %2};" : "=l"(p1) : "f"(m2), "f"(m3));
            asm("add.rn.f32x2 %0, %0, %1;" : "+l"(A) : "l"(p0));
            asm("add.rn.f32x2 %0, %0, %1;" : "+l"(B) : "l"(p1));
        }
        float a0, a1, b0, b1;
        asm("mov.b64 {%0, %1}, %2;" : "=f"(a0), "=f"(a1) : "l"(A));
        asm("mov.b64 {%0, %1}, %2;" : "=f"(b0), "=f"(b1) : "l"(B));
        float S = block_sum((a0 + a1) + (b0 + b1), red[pb], tid, lane); pb ^= 1;
        c = (S + 1e-20f) * invk;
    }

    // ---- gamma = min(e*g, 1), g = exp(a/0.3) = 1/c ----
    const float g = __fdividef(1.0f, c);
    float4* o4 = (float4*)(out + base);
    #pragma unroll
    for (int i = 0; i < EPT / 4; i++) {
        float4 r;
        r.x = fminf(s[4*i+0] * g, 1.0f);
        r.y = fminf(s[4*i+1] * g, 1.0f);
        r.z = fminf(s[4*i+2] * g, 1.0f);
        r.w = fminf(s[4*i+3] * g, 1.0f);
        o4[i * TPB + tid] = r;
    }
}

extern "C" void kernel_launch(void* const* d_in, const int* in_sizes, int n_in,
                              void* d_out, int out_size) {
    const float* score = (const float*)d_in[0];
    const int*   mask  = (const int*)d_in[1];
    float*       out   = (float*)d_out;
    int rows = in_sizes[0] / COLS;
    normalizer_kernel<<<rows, TPB>>>(score, mask, out);
}

// round 8
// speedup vs baseline: 1.4427x; 1.4427x over previous
#include <cuda_runtime.h>

#define COLS 8192
#define TPB  256
#define EPT  32            // 256*32 = 8192

__device__ __forceinline__ float ex2f(float x) {
    float y; asm("ex2.approx.ftz.f32 %0, %1;" : "=f"(y) : "f"(x)); return y;
}
__device__ __forceinline__ float lg2f(float x) {
    float y; asm("lg2.approx.ftz.f32 %0, %1;" : "=f"(y) : "f"(x)); return y;
}

// R4-proven block round: 1 STS/thread, warp0 alone reduces the 256 partials
// (2x LDS.128 + adds + shfl tree), lane0 applies the scalar update and
// broadcasts via smem. Two barriers; single-buffered is race-free (every
// conflicting access pair is separated by a full barrier).
// NOTE: call sites must fully parenthesize arguments containing commas.
#define BLOCK_ROUND(partial, lane0_expr)                                   \
    do {                                                                   \
        red[tid] = (partial);                                              \
        __syncthreads();                                                   \
        if (tid < 32) {                                                    \
            const float4* r4 = (const float4*)red;                         \
            float4 a0 = r4[tid * 2], a1 = r4[tid * 2 + 1];                 \
            float x = ((a0.x + a0.y) + (a0.z + a0.w)) +                    \
                      ((a1.x + a1.y) + (a1.z + a1.w));                     \
            _Pragma("unroll")                                              \
            for (int o = 16; o; o >>= 1)                                   \
                x += __shfl_xor_sync(0xffffffffu, x, o);                   \
            if (tid == 0) bc = (lane0_expr);                               \
        }                                                                  \
        __syncthreads();                                                   \
    } while (0)

// Annealed pass at stride ST (stratified subsample), scaled by ST.
// CAP=0 only when provably nothing can be capped (b == 0 effect-free).
template<int ST, int CAP>
__device__ __forceinline__ float pass_sum(const float* s, float na, float Kt) {
    float l0 = 0.f, l1 = 0.f;
    #pragma unroll
    for (int j = 0; j < EPT; j += 2 * ST) {
        float x0 = CAP ? fminf(s[j],      na) : s[j];
        float x1 = CAP ? fminf(s[j + ST], na) : s[j + ST];
        l0 += ex2f(x0 * Kt);
        l1 += ex2f(x1 * Kt);
    }
    return (l0 + l1) * (float)ST;
}

__global__ void __launch_bounds__(TPB, 4)
normalizer_kernel(const float* __restrict__ score,
                  const int*   __restrict__ mask,
                  float*       __restrict__ out) {
    __shared__ float  red[TPB];
    __shared__ float  bc;
    __shared__ float4 st4[TPB / 32];  // stats round scratch (one per warp)
    __shared__ float2 stbc;           // {invk, skip}

    const int tid  = threadIdx.x;
    const size_t base = (size_t)blockIdx.x * COLS;

    const float4* s4 = (const float4*)(score + base);
    const int4*   m4 = (const int4*)(mask + base);

    // ---- load + mask + stats (masked -> -1e30: exp->0, never capped) ----
    float s[EPT];
    float cnt = 0.f, sm = 0.f, mx = -1e30f;
    #pragma unroll
    for (int i = 0; i < EPT / 4; i++) {
        float4 v = s4[i * TPB + tid];
        int4   m = m4[i * TPB + tid];
        s[4*i+0] = m.x ? v.x : -1e30f;  cnt += m.x ? 1.f : 0.f;  sm += m.x ? v.x : 0.f;
        s[4*i+1] = m.y ? v.y : -1e30f;  cnt += m.y ? 1.f : 0.f;  sm += m.y ? v.y : 0.f;
        s[4*i+2] = m.z ? v.z : -1e30f;  cnt += m.z ? 1.f : 0.f;  sm += m.z ? v.z : 0.f;
        s[4*i+3] = m.w ? v.w : -1e30f;  cnt += m.w ? 1.f : 0.f;  sm += m.w ? v.w : 0.f;
        mx = fmaxf(fmaxf(mx, fmaxf(s[4*i+0], s[4*i+1])), fmaxf(s[4*i+2], s[4*i+3]));
    }

    // ---- stats round (count, sum, max): warp shfl reduce, one float4 per
    //      warp to smem, thread 0 finishes and publishes {invk, skip}. ----
    {
        const int lane = tid & 31, warp = tid >> 5;
        float c0 = cnt, c1 = sm, c2 = mx;
        #pragma unroll
        for (int o = 16; o; o >>= 1) {
            c0 += __shfl_xor_sync(0xffffffffu, c0, o);
            c1 += __shfl_xor_sync(0xffffffffu, c1, o);
            c2 = fmaxf(c2, __shfl_xor_sync(0xffffffffu, c2, o));
        }
        if (lane == 0) st4[warp] = make_float4(c0, c1, c2, 0.f);
        __syncthreads();
        if (tid == 0) {
            float n = 0.f, S = 0.f, M = -1e30f;
            #pragma unroll
            for (int w = 0; w < TPB / 32; w++) {
                float4 v = st4[w];
                n += v.x;  S += v.y;  M = fmaxf(M, v.z);
            }
            float invk = __fdividef(10.0f, n);       // 1/(0.1n)
            // Jensen: for an uncapped sum, na_t = theta_t*ln(S_t/k) >=
            // theta_t*ln(n/k) + mean(s) = theta_t*ln10 + mean(s).
            // theta2*ln10 = 4.513 > 4.45 margin. If that clears max(s),
            // rounds t=0..2 cap nothing -> exactly zero effect. Skip them.
            float skip = (__fdividef(S, n) + 4.45f >= M) ? 1.f : 0.f;
            stbc = make_float2(invk, skip);
        }
        __syncthreads();
    }
    const float invk = stbc.x;
    const bool  skip = (stbc.y != 0.f);

    const float L2E = 1.44269504088896340736f;
    const float LN2 = 0.6931471805599453f;
    // theta_t = max(0.7^t*4, 0.3): distinct t=0..7, then 0.3 for t=8..19.
    const float TH[8] = {4.0f, 2.8f, 1.96f, 1.372f, 0.9604f,
                         0.67228f, 0.470596f, 0.3294172f};

    float na;   // na = -a = theta*ln2*log2(S*invk)

    if (skip) {
        // start at t3 directly, uncapped, 1/4 subsample
        BLOCK_ROUND((pass_sum<4,0>(s, 0.f, L2E / TH[3])),
                    ((TH[3] * LN2) * lg2f((x + 1e-20f) * invk)));
        na = bc;
    } else {
        BLOCK_ROUND((pass_sum<4,0>(s, 0.f, L2E / TH[0])),
                    ((TH[0] * LN2) * lg2f((x + 1e-20f) * invk)));
        na = bc;
        #pragma unroll
        for (int t = 1; t < 4; t++) {
            BLOCK_ROUND((pass_sum<4,1>(s, na, L2E / TH[t])),
                        ((TH[t] * LN2) * lg2f((x + 1e-20f) * invk)));
            na = bc;
        }
    }
    // t4, t5 @ 1/4
    #pragma unroll
    for (int t = 4; t < 6; t++) {
        BLOCK_ROUND((pass_sum<4,1>(s, na, L2E / TH[t])),
                    ((TH[t] * LN2) * lg2f((x + 1e-20f) * invk)));
        na = bc;
    }
    // t6 @ 1/2
    BLOCK_ROUND((pass_sum<2,1>(s, na, L2E / TH[6])),
                ((TH[6] * LN2) * lg2f((x + 1e-20f) * invk)));
    na = bc;
    // t7 full
    BLOCK_ROUND((pass_sum<1,1>(s, na, L2E / TH[7])),
                ((TH[7] * LN2) * lg2f((x + 1e-20f) * invk)));
    na = bc;

    // ---- convert in place: s := exp(s/0.3) (monotone; min commutes) ----
    const float K03 = L2E / 0.3f;
    #pragma unroll
    for (int j = 0; j < EPT; j++) s[j] = ex2f(s[j] * K03);

    // ---- t=8..19 (theta=0.3): term = min(e,c); scalar update collapses to
    //      c_next = S/k exactly (log/exp cancel). MUFU-free. Uniform early
    //      break once the fixed point stops moving (remaining rounds are
    //      then output no-ops within fp32 resolution). ----
    float c = ex2f(na * K03);
    #pragma unroll 1
    for (int t = 0; t < 12; t++) {
        float l0 = 0.f, l1 = 0.f, l2 = 0.f, l3 = 0.f;
        #pragma unroll
        for (int j = 0; j < EPT; j += 4) {
            l0 += fminf(s[j+0], c);
            l1 += fminf(s[j+1], c);
            l2 += fminf(s[j+2], c);
            l3 += fminf(s[j+3], c);
        }
        BLOCK_ROUND(((l0 + l1) + (l2 + l3)), ((x + 1e-20f) * invk));
        float cn = bc;                 // block-uniform
        bool done = fabsf(cn - c) <= 1e-6f * c;
        c = cn;
        if (done) break;               // uniform across the CTA
    }

    // ---- gamma = min(e*g, 1), g = exp(a/0.3) = 1/c ----
    const float g = __fdividef(1.0f, c);
    float4* o4 = (float4*)(out + base);
    #pragma unroll
    for (int i = 0; i < EPT / 4; i++) {
        float4 r;
        r.x = fminf(s[4*i+0] * g, 1.0f);
        r.y = fminf(s[4*i+1] * g, 1.0f);
        r.z = fminf(s[4*i+2] * g, 1.0f);
        r.w = fminf(s[4*i+3] * g, 1.0f);
        o4[i * TPB + tid] = r;
    }
}

extern "C" void kernel_launch(void* const* d_in, const int* in_sizes, int n_in,
                              void* d_out, int out_size) {
    const float* score = (const float*)d_in[0];
    const int*   mask  = (const int*)d_in[1];
    float*       out   = (float*)d_out;
    int rows = in_sizes[0] / COLS;
    normalizer_kernel<<<rows, TPB>>>(score, mask, out);
}